// round 15
// baseline (speedup 1.0000x reference)
#include <cuda_runtime.h>
#include <cuda_fp16.h>
#include <cstdint>

#define D 128
#define MAXN 100000
#define MAXE 1600000
#define CAP 128
#define MAXTILES ((MAXN + 127) / 128)   // 782

// ---------------- scratch (device globals; no allocations allowed) ----------
__device__ int   g_cnt [MAXN];                     // per-dst count (kept 0)
__device__ int   g_csr [(size_t)MAXN * CAP];       // padded buckets of src idx
__device__ uint2 g_self16[(size_t)MAXN * 32];      // A @ Wr^T + b, fp16 rows
__device__ uint2 g_xl16[(size_t)MAXN * 32];        // messages A@Wl^T, fp16 rows
// fp16 staging, row-major [row][128] fp16 (16 uint4 per row) — layer-2 GEMM input
__device__ uint4 g_x16[(size_t)MAXTILES * 2048];
__device__ uint4 g_w16[2 * 4096];  // per layer: [Wl;Wr] stacked = 256 rows, fp16

// ---------------- streams/events for fork-join capture ----------------------
static cudaStream_t s_side = nullptr;
static cudaEvent_t  s_fork = nullptr, s_join = nullptr;
namespace {
struct SideInit {
    SideInit() {
        cudaStreamCreateWithFlags(&s_side, cudaStreamNonBlocking);
        cudaEventCreateWithFlags(&s_fork, cudaEventDisableTiming);
        cudaEventCreateWithFlags(&s_join, cudaEventDisableTiming);
    }
};
SideInit s_sideInit;
}

// ---------------- small helpers ---------------------------------------------
__device__ __forceinline__ int load_idx(const void* p, int is64, long long i) {
    if (is64) return (int)((const long long*)p)[i];
    return ((const int*)p)[i];
}

// per-block probe: int64 edge buffer has all-zero high words in first 128 elems
__device__ __forceinline__ int probe_is64(const void* edge, int E) {
    int t = threadIdx.x;
    unsigned hw = 0;
    if (t < 128 && t < E) hw = ((const unsigned*)edge)[2 * t + 1];
    int any = __syncthreads_or(hw != 0);
    return !any;
}

// single-pass padded-bucket CSR fill (g_cnt zero on entry; re-zeroed by pull2)
__global__ void fill_kernel(const void* __restrict__ edge, int E) {
    const int is64 = probe_is64(edge, E);
    const long long t0 = blockIdx.x * (long long)blockDim.x + threadIdx.x;
    const long long stride2 = ((long long)gridDim.x * blockDim.x) * 2;
    long long e = t0 * 2;
    for (; e + 2 <= E; e += stride2) {
        int s0 = load_idx(edge, is64, e + 0);
        int s1 = load_idx(edge, is64, e + 1);
        int d0 = load_idx(edge, is64, (long long)E + e + 0);
        int d1 = load_idx(edge, is64, (long long)E + e + 1);
        int p0 = atomicAdd(&g_cnt[d0], 1);
        int p1 = atomicAdd(&g_cnt[d1], 1);
        if (p0 < CAP) g_csr[(size_t)d0 * CAP + p0] = s0;
        if (p1 < CAP) g_csr[(size_t)d1 * CAP + p1] = s1;
    }
    for (; e < E; e++) {
        int s = load_idx(edge, is64, e);
        int d = load_idx(edge, is64, (long long)E + e);
        int pos = atomicAdd(&g_cnt[d], 1);
        if (pos < CAP) g_csr[(size_t)d * CAP + pos] = s;
    }
}

// ---------------- weight conversion: fp32 -> fp16 ---------------------------
__global__ void conv_w_kernel(const float* __restrict__ W0, const float* __restrict__ W1,
                              const float* __restrict__ W2, const float* __restrict__ W3) {
    int c = blockIdx.x * blockDim.x + threadIdx.x;   // 0 .. 4*2048-1
    if (c >= 4 * 2048) return;
    int which = c >> 11;
    int local = c & 2047;
    int row = local >> 4, kc = local & 15;
    const float* W = (which == 0) ? W0 : (which == 1) ? W1 : (which == 2) ? W2 : W3;
    const float4* ap = (const float4*)(W + (size_t)row * D + kc * 8);
    float4 a = ap[0], b = ap[1];
    float v[8] = {a.x, a.y, a.z, a.w, b.x, b.y, b.z, b.w};
    unsigned hw[4];
#pragma unroll
    for (int i = 0; i < 4; i++) {
        __half2 h = __floats2half2_rn(v[2*i], v[2*i+1]);
        hw[i] = *(unsigned*)&h;
    }
    int layer = which >> 1, half = which & 1;
    long long o = (long long)layer * 4096 + half * 2048 + local;
    g_w16[o] = make_uint4(hw[0], hw[1], hw[2], hw[3]);
}

// ---------------- mma.sync fp16 GEMM with ldmatrix ---------------------------
__device__ __forceinline__ void mma16816(float* acc, const unsigned* a,
                                         const unsigned* b) {
    asm volatile(
        "mma.sync.aligned.m16n8k16.row.col.f32.f16.f16.f32 "
        "{%0,%1,%2,%3}, {%4,%5,%6,%7}, {%8,%9}, {%0,%1,%2,%3};"
        : "+f"(acc[0]), "+f"(acc[1]), "+f"(acc[2]), "+f"(acc[3])
        : "r"(a[0]), "r"(a[1]), "r"(a[2]), "r"(a[3]), "r"(b[0]), "r"(b[1]));
}
__device__ __forceinline__ void ldsm4(unsigned* r, uint32_t a) {
    asm volatile("ldmatrix.sync.aligned.m8n8.x4.shared.b16 {%0,%1,%2,%3}, [%4];"
        : "=r"(r[0]), "=r"(r[1]), "=r"(r[2]), "=r"(r[3]) : "r"(a));
}
__device__ __forceinline__ uint32_t smem_u32(const void* p) {
    uint32_t a;
    asm("{ .reg .u64 t; cvta.to.shared.u64 t, %1; cvt.u32.u64 %0, t; }"
        : "=r"(a) : "l"(p));
    return a;
}
__device__ __forceinline__ void acc_m(float4& acc, uint2 m) {
    float2 f0 = __half22float2(*(__half2*)&m.x);
    float2 f1 = __half22float2(*(__half2*)&m.y);
    acc.x += f0.x; acc.y += f0.y; acc.z += f1.x; acc.w += f1.y;
}

// SMEM row = 272B (17 uint4): ldmatrix 8-row phases -> conflict-free
#define RS16 17
#define RSB  272
#define A4   0
#define W4L  2176
#define W4R  4352
#define SMEMB 104448

// dual-output GEMM: one block per 128-row tile; A staged once, both W tiles
// staged; two accumulation passes -> xl16 (Wl) and self16 (Wr + bias)
__global__ __launch_bounds__(512, 1)
void gemm_tc_kernel(const float* __restrict__ bias, int layer,
                    int N, const float* __restrict__ a32) {
    extern __shared__ uint4 smem4[];

    const int tid  = threadIdx.x;
    const int wid  = tid >> 5;
    const int lane = tid & 31;
    const int tile = blockIdx.x;

    const int mrow = (wid & 3) * 32;
    const int ncol = (wid >> 2) * 32;

    // ---- stage A and BOTH output W tiles ----
    {
        const uint4* wl = g_w16 + (size_t)layer * 4096;
        const uint4* wr = wl + 2048;
        if (a32) {
#pragma unroll
            for (int i = tid; i < 2048; i += 512) {
                int r = i >> 4, c = i & 15;
                int grow = tile * 128 + r;
                unsigned wd[4] = {0u, 0u, 0u, 0u};
                if (grow < N) {
                    const float4* ap = (const float4*)(a32 + (size_t)grow * D + c * 8);
                    float4 f0 = ap[0], f1 = ap[1];
                    __half2 h;
                    h = __floats2half2_rn(f0.x, f0.y); wd[0] = *(unsigned*)&h;
                    h = __floats2half2_rn(f0.z, f0.w); wd[1] = *(unsigned*)&h;
                    h = __floats2half2_rn(f1.x, f1.y); wd[2] = *(unsigned*)&h;
                    h = __floats2half2_rn(f1.z, f1.w); wd[3] = *(unsigned*)&h;
                }
                smem4[A4  + r * RS16 + c] = make_uint4(wd[0], wd[1], wd[2], wd[3]);
                smem4[W4L + r * RS16 + c] = wl[i];
                smem4[W4R + r * RS16 + c] = wr[i];
            }
        } else {
            const uint4* ga = g_x16 + (size_t)tile * 2048;
#pragma unroll
            for (int i = tid; i < 2048; i += 512) {
                int r = i >> 4, c = i & 15;
                smem4[A4  + r * RS16 + c] = ga[i];
                smem4[W4L + r * RS16 + c] = wl[i];
                smem4[W4R + r * RS16 + c] = wr[i];
            }
        }
    }
    __syncthreads();

    const uint32_t sb = smem_u32(smem4);
    const uint32_t aoff = (uint32_t)((mrow + (lane & 15)) * RSB + (lane >> 4) * 16);
    const uint32_t a0 = sb + A4 * 16 + aoff;
    const uint32_t a1 = a0 + 16 * RSB;
    const int msel = lane >> 3;
    const uint32_t woff = (uint32_t)((ncol + ((msel >> 1) * 8) + (lane & 7)) * RSB +
                                     (msel & 1) * 16);
    const int q = lane & 3, g = lane >> 2;

#pragma unroll
    for (int osel = 0; osel < 2; osel++) {
        const uint32_t w0 = sb + (osel ? W4R : W4L) * 16 + woff;
        const uint32_t w1 = w0 + 16 * RSB;

        float acc[2][4][4];
#pragma unroll
        for (int mt = 0; mt < 2; mt++)
#pragma unroll
            for (int nt = 0; nt < 4; nt++)
#pragma unroll
                for (int i = 0; i < 4; i++) acc[mt][nt][i] = 0.f;

#pragma unroll
        for (int kc = 0; kc < 8; kc++) {
            const uint32_t kb = kc * 32;
            unsigned af[2][4], wf[2][4];
            ldsm4(af[0], a0 + kb); ldsm4(af[1], a1 + kb);
            ldsm4(wf[0], w0 + kb); ldsm4(wf[1], w1 + kb);
#pragma unroll
            for (int mt = 0; mt < 2; mt++)
#pragma unroll
                for (int nt = 0; nt < 4; nt++)
                    mma16816(acc[mt][nt], af[mt], &wf[nt >> 1][(nt & 1) * 2]);
        }

        __half* op = (__half*)(osel ? g_self16 : g_xl16);
#pragma unroll
        for (int nt = 0; nt < 4; nt++) {
            int col = ncol + nt * 8 + q * 2;
            float b0 = 0.f, b1 = 0.f;
            if (osel) { b0 = __ldg(bias + col); b1 = __ldg(bias + col + 1); }
#pragma unroll
            for (int mt = 0; mt < 2; mt++) {
                int r = tile * 128 + mrow + mt * 16 + g;
                if (r < N)
                    *(__half2*)(op + (size_t)r * D + col) =
                        __floats2half2_rn(acc[mt][nt][0] + b0, acc[mt][nt][1] + b1);
                if (r + 8 < N)
                    *(__half2*)(op + (size_t)(r + 8) * D + col) =
                        __floats2half2_rn(acc[mt][nt][2] + b0, acc[mt][nt][3] + b1);
            }
        }
    }
}

// ---------------- bucket pull: out = [relu](self + mean_agg(xl16)) ----------
// warp per node; fp16 gather, fp32 accumulate; 8-wide MLP batching.
// zeroCnt: re-zero g_cnt after use (last consumer keeps replay invariant).
__global__ void pull_kernel(float* __restrict__ out32, int writeStage,
                            int N, int Npad, int doRelu, int zeroCnt) {
    const int lane = threadIdx.x & 31;
    long long w  = (blockIdx.x * (long long)blockDim.x + threadIdx.x) >> 5;
    long long nw = ((long long)gridDim.x * blockDim.x) >> 5;

    uint2* stage = (uint2*)g_x16;

    for (long long node = w; node < Npad; node += nw) {
        if (node < N) {
            const int cnt = g_cnt[node];
            const int beg = (int)(node * CAP);
            const int end = beg + min(cnt, CAP);
            float4 acc = make_float4(0.f, 0.f, 0.f, 0.f);
            int e = beg;
            for (; e + 8 <= end; e += 8) {
                int s0 = __ldg(g_csr + e + 0);
                int s1 = __ldg(g_csr + e + 1);
                int s2 = __ldg(g_csr + e + 2);
                int s3 = __ldg(g_csr + e + 3);
                int s4 = __ldg(g_csr + e + 4);
                int s5 = __ldg(g_csr + e + 5);
                int s6 = __ldg(g_csr + e + 6);
                int s7 = __ldg(g_csr + e + 7);
                uint2 m0 = g_xl16[(size_t)s0 * 32 + lane];
                uint2 m1 = g_xl16[(size_t)s1 * 32 + lane];
                uint2 m2 = g_xl16[(size_t)s2 * 32 + lane];
                uint2 m3 = g_xl16[(size_t)s3 * 32 + lane];
                uint2 m4 = g_xl16[(size_t)s4 * 32 + lane];
                uint2 m5 = g_xl16[(size_t)s5 * 32 + lane];
                uint2 m6 = g_xl16[(size_t)s6 * 32 + lane];
                uint2 m7 = g_xl16[(size_t)s7 * 32 + lane];
                acc_m(acc, m0); acc_m(acc, m1); acc_m(acc, m2); acc_m(acc, m3);
                acc_m(acc, m4); acc_m(acc, m5); acc_m(acc, m6); acc_m(acc, m7);
            }
            if (e + 4 <= end) {
                int s0 = __ldg(g_csr + e + 0);
                int s1 = __ldg(g_csr + e + 1);
                int s2 = __ldg(g_csr + e + 2);
                int s3 = __ldg(g_csr + e + 3);
                uint2 m0 = g_xl16[(size_t)s0 * 32 + lane];
                uint2 m1 = g_xl16[(size_t)s1 * 32 + lane];
                uint2 m2 = g_xl16[(size_t)s2 * 32 + lane];
                uint2 m3 = g_xl16[(size_t)s3 * 32 + lane];
                acc_m(acc, m0); acc_m(acc, m1); acc_m(acc, m2); acc_m(acc, m3);
                e += 4;
            }
            for (; e < end; e++) {
                int s = __ldg(g_csr + e);
                acc_m(acc, g_xl16[(size_t)s * 32 + lane]);
            }
            float inv = 1.0f / fmaxf((float)cnt, 1.0f);
            uint2 s16 = g_self16[(size_t)node * 32 + lane];
            float2 sv0 = __half22float2(*(__half2*)&s16.x);
            float2 sv1 = __half22float2(*(__half2*)&s16.y);
            float4 o;
            o.x = sv0.x + acc.x * inv; o.y = sv0.y + acc.y * inv;
            o.z = sv1.x + acc.z * inv; o.w = sv1.y + acc.w * inv;
            if (doRelu) {
                o.x = fmaxf(o.x, 0.f); o.y = fmaxf(o.y, 0.f);
                o.z = fmaxf(o.z, 0.f); o.w = fmaxf(o.w, 0.f);
            }
            if (out32)
                *(float4*)(out32 + (size_t)node * D + lane * 4) = o;
            if (writeStage) {
                uint2 p;
                __half2 h0 = __floats2half2_rn(o.x, o.y);
                __half2 h1 = __floats2half2_rn(o.z, o.w);
                p.x = *(unsigned*)&h0; p.y = *(unsigned*)&h1;
                stage[(size_t)node * 32 + lane] = p;
            }
            if (zeroCnt && lane == 0) g_cnt[node] = 0;
        } else if (writeStage) {
            stage[(size_t)node * 32 + lane] = make_uint2(0u, 0u);
        }
    }
}

// ---------------- launch ------------------------------------------------------
extern "C" void kernel_launch(void* const* d_in, const int* in_sizes, int n_in,
                              void* d_out, int out_size) {
    const float* x    = (const float*)d_in[0];
    const void*  edge = d_in[1];
    const float* Wl1  = (const float*)d_in[2];
    const float* Wr1  = (const float*)d_in[3];
    const float* b1   = (const float*)d_in[4];
    const float* Wl2  = (const float*)d_in[5];
    const float* Wr2  = (const float*)d_in[6];
    const float* b2   = (const float*)d_in[7];
    float* out = (float*)d_out;

    const int N = in_sizes[0] / D;
    const int E = in_sizes[1] / 2;
    const int tiles = (N + 127) / 128;
    const int Npad = tiles * 128;

    cudaFuncSetAttribute(gemm_tc_kernel,
                         cudaFuncAttributeMaxDynamicSharedMemorySize, SMEMB);

    // ---- fork: side branch = conv_w -> gemm1 (independent of bucket fill) ----
    cudaEventRecord(s_fork, 0);                       // legacy default stream
    cudaStreamWaitEvent(s_side, s_fork, 0);
    conv_w_kernel<<<32, 256, 0, s_side>>>(Wl1, Wr1, Wl2, Wr2);
    gemm_tc_kernel<<<tiles, 512, SMEMB, s_side>>>(b1, 0, N, x);
    cudaEventRecord(s_join, s_side);

    // ---- main branch: single-pass padded-bucket CSR fill ----
    fill_kernel<<<1024, 256>>>(edge, E);

    // ---- join, then the dependent tail ----
    cudaStreamWaitEvent(0, s_join, 0);
    pull_kernel<<<tiles * 16, 256>>>(nullptr, /*stage=*/1, N, Npad,
                                     /*relu=*/1, /*zeroCnt=*/0);
    gemm_tc_kernel<<<tiles, 512, SMEMB>>>(b2, 1, N, nullptr);
    pull_kernel<<<tiles * 16, 256>>>(out, /*stage=*/0, N, Npad,
                                     /*relu=*/0, /*zeroCnt=*/1);
}

// round 16
// speedup vs baseline: 1.0044x; 1.0044x over previous
#include <cuda_runtime.h>
#include <cuda_fp16.h>
#include <cstdint>

#define D 128
#define MAXN 100000
#define MAXE 1600000
#define MAXTILES ((MAXN + 127) / 128)   // 782

// ---------------- scratch (device globals; no allocations allowed) ----------
__device__ float g_inv [MAXN];                     // 1/max(deg,1)
__device__ int   g_cnt [MAXN];                     // degree histogram (kept 0)
__device__ int   g_off [MAXN + 1];                 // CSR offsets
__device__ int   g_cur [MAXN];                     // fill cursors
__device__ int   g_csr [MAXE];                     // src indices bucketed by dst
__device__ uint2 g_self16[(size_t)MAXN * 32];      // A @ Wr^T + b, fp16 rows
__device__ uint2 g_xl16[(size_t)MAXN * 32];        // messages A@Wl^T, fp16 rows
// fp16 staging, row-major [row][128] fp16 (16 uint4 per row) — layer-2 GEMM input
__device__ uint4 g_x16[(size_t)MAXTILES * 2048];
__device__ uint4 g_w16[2 * 4096];  // per layer: [Wl;Wr] stacked = 256 rows, fp16
__device__ int   g_bsum[512];

// ---------------- streams/events for fork-join capture ----------------------
static cudaStream_t s_side = nullptr;
static cudaEvent_t  s_fork = nullptr, s_join = nullptr;
namespace {
struct SideInit {
    SideInit() {
        cudaStreamCreateWithFlags(&s_side, cudaStreamNonBlocking);
        cudaEventCreateWithFlags(&s_fork, cudaEventDisableTiming);
        cudaEventCreateWithFlags(&s_join, cudaEventDisableTiming);
    }
};
SideInit s_sideInit;
}

// ---------------- small helpers ---------------------------------------------
__device__ __forceinline__ int load_idx(const void* p, int is64, long long i) {
    if (is64) return (int)((const long long*)p)[i];
    return ((const int*)p)[i];
}

// per-block probe: int64 edge buffer has all-zero high words in first 128 elems
__device__ __forceinline__ int probe_is64(const void* edge, int E) {
    int t = threadIdx.x;
    unsigned hw = 0;
    if (t < 128 && t < E) hw = ((const unsigned*)edge)[2 * t + 1];
    int any = __syncthreads_or(hw != 0);
    return !any;
}

// degree histogram, 4-way unrolled (g_cnt zero on entry; re-zeroed by scan3)
__global__ void deg_kernel(const void* __restrict__ edge, int E) {
    const int is64 = probe_is64(edge, E);
    const long long t0 = blockIdx.x * (long long)blockDim.x + threadIdx.x;
    const long long stride4 = ((long long)gridDim.x * blockDim.x) * 4;
    long long e = t0 * 4;
    for (; e + 4 <= E; e += stride4) {
        int d0 = load_idx(edge, is64, (long long)E + e + 0);
        int d1 = load_idx(edge, is64, (long long)E + e + 1);
        int d2 = load_idx(edge, is64, (long long)E + e + 2);
        int d3 = load_idx(edge, is64, (long long)E + e + 3);
        atomicAdd(&g_cnt[d0], 1);
        atomicAdd(&g_cnt[d1], 1);
        atomicAdd(&g_cnt[d2], 1);
        atomicAdd(&g_cnt[d3], 1);
    }
    for (; e < E; e++) {
        int d = load_idx(edge, is64, (long long)E + e);
        atomicAdd(&g_cnt[d], 1);
    }
}

// ---- scan: stage1 block sums, stage2 fused into stage3 ---------------------
__global__ void scan1_kernel(int N) {
    __shared__ int sh[256];
    int i = blockIdx.x * 256 + threadIdx.x;
    sh[threadIdx.x] = (i < N) ? g_cnt[i] : 0;
    __syncthreads();
#pragma unroll
    for (int s = 128; s > 0; s >>= 1) {
        if (threadIdx.x < s) sh[threadIdx.x] += sh[threadIdx.x + s];
        __syncthreads();
    }
    if (threadIdx.x == 0) g_bsum[blockIdx.x] = sh[0];
}

__global__ void scan3_kernel(int N, int E) {
    __shared__ int sh[256];
    __shared__ int red[256];
    const int t = threadIdx.x;
    const int i = blockIdx.x * 256 + t;

    int acc = 0;
    for (int j = t; j < blockIdx.x; j += 256) acc += g_bsum[j];
    red[t] = acc;
    __syncthreads();
#pragma unroll
    for (int s = 128; s > 0; s >>= 1) {
        if (t < s) red[t] += red[t + s];
        __syncthreads();
    }
    const int base = red[0];

    int v = (i < N) ? g_cnt[i] : 0;
    sh[t] = v;
    __syncthreads();
#pragma unroll
    for (int s = 1; s < 256; s <<= 1) {
        int u = (t >= s) ? sh[t - s] : 0;
        __syncthreads();
        sh[t] += u;
        __syncthreads();
    }
    if (i < N) {
        int excl = base + sh[t] - v;
        g_off[i] = excl;
        g_cur[i] = excl;
        g_inv[i] = 1.0f / fmaxf((float)v, 1.0f);
        g_cnt[i] = 0;                 // keep zeroed for the next call (replay)
    }
    if (i == N - 1) g_off[N] = E;
}

// CSR bucket fill, 2-way unrolled (atomic cursors)
__global__ void build_csr_kernel(const void* __restrict__ edge, int E) {
    const int is64 = probe_is64(edge, E);
    const long long t0 = blockIdx.x * (long long)blockDim.x + threadIdx.x;
    const long long stride2 = ((long long)gridDim.x * blockDim.x) * 2;
    long long e = t0 * 2;
    for (; e + 2 <= E; e += stride2) {
        int s0 = load_idx(edge, is64, e + 0);
        int s1 = load_idx(edge, is64, e + 1);
        int d0 = load_idx(edge, is64, (long long)E + e + 0);
        int d1 = load_idx(edge, is64, (long long)E + e + 1);
        int p0 = atomicAdd(&g_cur[d0], 1);
        int p1 = atomicAdd(&g_cur[d1], 1);
        g_csr[p0] = s0;
        g_csr[p1] = s1;
    }
    for (; e < E; e++) {
        int s = load_idx(edge, is64, e);
        int d = load_idx(edge, is64, (long long)E + e);
        int pos = atomicAdd(&g_cur[d], 1);
        g_csr[pos] = s;
    }
}

// ---------------- weight conversion: fp32 -> fp16 ---------------------------
__global__ void conv_w_kernel(const float* __restrict__ W0, const float* __restrict__ W1,
                              const float* __restrict__ W2, const float* __restrict__ W3) {
    int c = blockIdx.x * blockDim.x + threadIdx.x;   // 0 .. 4*2048-1
    if (c >= 4 * 2048) return;
    int which = c >> 11;
    int local = c & 2047;
    int row = local >> 4, kc = local & 15;
    const float* W = (which == 0) ? W0 : (which == 1) ? W1 : (which == 2) ? W2 : W3;
    const float4* ap = (const float4*)(W + (size_t)row * D + kc * 8);
    float4 a = ap[0], b = ap[1];
    float v[8] = {a.x, a.y, a.z, a.w, b.x, b.y, b.z, b.w};
    unsigned hw[4];
#pragma unroll
    for (int i = 0; i < 4; i++) {
        __half2 h = __floats2half2_rn(v[2*i], v[2*i+1]);
        hw[i] = *(unsigned*)&h;
    }
    int layer = which >> 1, half = which & 1;
    long long o = (long long)layer * 4096 + half * 2048 + local;
    g_w16[o] = make_uint4(hw[0], hw[1], hw[2], hw[3]);
}

// ---------------- mma.sync fp16 GEMM with ldmatrix ---------------------------
__device__ __forceinline__ void mma16816(float* acc, const unsigned* a,
                                         const unsigned* b) {
    asm volatile(
        "mma.sync.aligned.m16n8k16.row.col.f32.f16.f16.f32 "
        "{%0,%1,%2,%3}, {%4,%5,%6,%7}, {%8,%9}, {%0,%1,%2,%3};"
        : "+f"(acc[0]), "+f"(acc[1]), "+f"(acc[2]), "+f"(acc[3])
        : "r"(a[0]), "r"(a[1]), "r"(a[2]), "r"(a[3]), "r"(b[0]), "r"(b[1]));
}
__device__ __forceinline__ void ldsm4(unsigned* r, uint32_t a) {
    asm volatile("ldmatrix.sync.aligned.m8n8.x4.shared.b16 {%0,%1,%2,%3}, [%4];"
        : "=r"(r[0]), "=r"(r[1]), "=r"(r[2]), "=r"(r[3]) : "r"(a));
}
__device__ __forceinline__ uint32_t smem_u32(const void* p) {
    uint32_t a;
    asm("{ .reg .u64 t; cvta.to.shared.u64 t, %1; cvt.u32.u64 %0, t; }"
        : "=r"(a) : "l"(p));
    return a;
}

// SMEM row = 272B (17 uint4): ldmatrix 8-row phases -> conflict-free
#define RS16 17
#define RSB  272
#define A4   0
#define W4L  2176
#define W4R  4352
#define SMEMB 104448

// dual-output GEMM: one block per 128-row tile; A staged once, both W tiles
// staged; two accumulation passes -> xl16 (Wl) and self16 (Wr + bias)
__global__ __launch_bounds__(512, 1)
void gemm_tc_kernel(const float* __restrict__ bias, int layer,
                    int N, const float* __restrict__ a32) {
    extern __shared__ uint4 smem4[];

    const int tid  = threadIdx.x;
    const int wid  = tid >> 5;
    const int lane = tid & 31;
    const int tile = blockIdx.x;

    const int mrow = (wid & 3) * 32;
    const int ncol = (wid >> 2) * 32;

    // ---- stage A and BOTH output W tiles ----
    {
        const uint4* wl = g_w16 + (size_t)layer * 4096;
        const uint4* wr = wl + 2048;
        if (a32) {
#pragma unroll
            for (int i = tid; i < 2048; i += 512) {
                int r = i >> 4, c = i & 15;
                int grow = tile * 128 + r;
                unsigned wd[4] = {0u, 0u, 0u, 0u};
                if (grow < N) {
                    const float4* ap = (const float4*)(a32 + (size_t)grow * D + c * 8);
                    float4 f0 = ap[0], f1 = ap[1];
                    __half2 h;
                    h = __floats2half2_rn(f0.x, f0.y); wd[0] = *(unsigned*)&h;
                    h = __floats2half2_rn(f0.z, f0.w); wd[1] = *(unsigned*)&h;
                    h = __floats2half2_rn(f1.x, f1.y); wd[2] = *(unsigned*)&h;
                    h = __floats2half2_rn(f1.z, f1.w); wd[3] = *(unsigned*)&h;
                }
                smem4[A4  + r * RS16 + c] = make_uint4(wd[0], wd[1], wd[2], wd[3]);
                smem4[W4L + r * RS16 + c] = wl[i];
                smem4[W4R + r * RS16 + c] = wr[i];
            }
        } else {
            const uint4* ga = g_x16 + (size_t)tile * 2048;
#pragma unroll
            for (int i = tid; i < 2048; i += 512) {
                int r = i >> 4, c = i & 15;
                smem4[A4  + r * RS16 + c] = ga[i];
                smem4[W4L + r * RS16 + c] = wl[i];
                smem4[W4R + r * RS16 + c] = wr[i];
            }
        }
    }
    __syncthreads();

    const uint32_t sb = smem_u32(smem4);
    const uint32_t aoff = (uint32_t)((mrow + (lane & 15)) * RSB + (lane >> 4) * 16);
    const uint32_t a0 = sb + A4 * 16 + aoff;
    const uint32_t a1 = a0 + 16 * RSB;
    const int msel = lane >> 3;
    const uint32_t woff = (uint32_t)((ncol + ((msel >> 1) * 8) + (lane & 7)) * RSB +
                                     (msel & 1) * 16);
    const int q = lane & 3, g = lane >> 2;

#pragma unroll
    for (int osel = 0; osel < 2; osel++) {
        const uint32_t w0 = sb + (osel ? W4R : W4L) * 16 + woff;
        const uint32_t w1 = w0 + 16 * RSB;

        float acc[2][4][4];
#pragma unroll
        for (int mt = 0; mt < 2; mt++)
#pragma unroll
            for (int nt = 0; nt < 4; nt++)
#pragma unroll
                for (int i = 0; i < 4; i++) acc[mt][nt][i] = 0.f;

#pragma unroll
        for (int kc = 0; kc < 8; kc++) {
            const uint32_t kb = kc * 32;
            unsigned af[2][4], wf[2][4];
            ldsm4(af[0], a0 + kb); ldsm4(af[1], a1 + kb);
            ldsm4(wf[0], w0 + kb); ldsm4(wf[1], w1 + kb);
#pragma unroll
            for (int mt = 0; mt < 2; mt++)
#pragma unroll
                for (int nt = 0; nt < 4; nt++)
                    mma16816(acc[mt][nt], af[mt], &wf[nt >> 1][(nt & 1) * 2]);
        }

        __half* op = (__half*)(osel ? g_self16 : g_xl16);
#pragma unroll
        for (int nt = 0; nt < 4; nt++) {
            int col = ncol + nt * 8 + q * 2;
            float b0 = 0.f, b1 = 0.f;
            if (osel) { b0 = __ldg(bias + col); b1 = __ldg(bias + col + 1); }
#pragma unroll
            for (int mt = 0; mt < 2; mt++) {
                int r = tile * 128 + mrow + mt * 16 + g;
                if (r < N)
                    *(__half2*)(op + (size_t)r * D + col) =
                        __floats2half2_rn(acc[mt][nt][0] + b0, acc[mt][nt][1] + b1);
                if (r + 8 < N)
                    *(__half2*)(op + (size_t)(r + 8) * D + col) =
                        __floats2half2_rn(acc[mt][nt][2] + b0, acc[mt][nt][3] + b1);
            }
        }
    }
}

// ---------------- CSR pull: half-warp per edge -------------------------------
// warp per node; lanes 0-15 handle even edges, 16-31 odd edges; each lane
// loads uint4 (8 fp16 dims). Cross-half shfl reduction at the end.
__device__ __forceinline__ void acc8(float* a, uint4 m) {
    float2 f;
    f = __half22float2(*(__half2*)&m.x); a[0] += f.x; a[1] += f.y;
    f = __half22float2(*(__half2*)&m.y); a[2] += f.x; a[3] += f.y;
    f = __half22float2(*(__half2*)&m.z); a[4] += f.x; a[5] += f.y;
    f = __half22float2(*(__half2*)&m.w); a[6] += f.x; a[7] += f.y;
}

__global__ void pull_kernel(float* __restrict__ out32, int writeStage,
                            int N, int Npad, int doRelu) {
    const int lane = threadIdx.x & 31;
    const int half = lane >> 4;        // 0: even edge, 1: odd edge
    const int hl   = lane & 15;        // uint4 index within 256B row
    long long w  = (blockIdx.x * (long long)blockDim.x + threadIdx.x) >> 5;
    long long nw = ((long long)gridDim.x * blockDim.x) >> 5;

    const uint4* xl   = (const uint4*)g_xl16;
    const uint4* self = (const uint4*)g_self16;
    uint4* stage = g_x16;

    for (long long node = w; node < Npad; node += nw) {
        if (node < N) {
            const int beg = g_off[node], end = g_off[node + 1];
            float acc[8];
#pragma unroll
            for (int i = 0; i < 8; i++) acc[i] = 0.f;

            int e = beg;
            for (; e + 4 <= end; e += 4) {
                int sA = __ldg(g_csr + e + half);
                int sB = __ldg(g_csr + e + 2 + half);
                uint4 mA = xl[(size_t)sA * 16 + hl];
                uint4 mB = xl[(size_t)sB * 16 + hl];
                acc8(acc, mA);
                acc8(acc, mB);
            }
            if (e + 2 <= end) {
                int s = __ldg(g_csr + e + half);
                uint4 m = xl[(size_t)s * 16 + hl];
                acc8(acc, m);
                e += 2;
            }
            if (e < end && half == 0) {
                int s = __ldg(g_csr + e);
                uint4 m = xl[(size_t)s * 16 + hl];
                acc8(acc, m);
            }

            // combine the two edge-halves (lanes 0-15 get the full sums)
#pragma unroll
            for (int i = 0; i < 8; i++)
                acc[i] += __shfl_down_sync(0xffffffffu, acc[i], 16);

            if (half == 0) {
                float inv = g_inv[node];
                uint4 s16 = self[(size_t)node * 16 + hl];
                float2 f0 = __half22float2(*(__half2*)&s16.x);
                float2 f1 = __half22float2(*(__half2*)&s16.y);
                float2 f2 = __half22float2(*(__half2*)&s16.z);
                float2 f3 = __half22float2(*(__half2*)&s16.w);
                float o[8];
                o[0] = f0.x + acc[0] * inv; o[1] = f0.y + acc[1] * inv;
                o[2] = f1.x + acc[2] * inv; o[3] = f1.y + acc[3] * inv;
                o[4] = f2.x + acc[4] * inv; o[5] = f2.y + acc[5] * inv;
                o[6] = f3.x + acc[6] * inv; o[7] = f3.y + acc[7] * inv;
                if (doRelu) {
#pragma unroll
                    for (int i = 0; i < 8; i++) o[i] = fmaxf(o[i], 0.f);
                }
                if (out32) {
                    float4* dst = (float4*)(out32 + (size_t)node * D + hl * 8);
                    dst[0] = make_float4(o[0], o[1], o[2], o[3]);
                    dst[1] = make_float4(o[4], o[5], o[6], o[7]);
                }
                if (writeStage) {
                    __half2 h0 = __floats2half2_rn(o[0], o[1]);
                    __half2 h1 = __floats2half2_rn(o[2], o[3]);
                    __half2 h2 = __floats2half2_rn(o[4], o[5]);
                    __half2 h3 = __floats2half2_rn(o[6], o[7]);
                    stage[(size_t)node * 16 + hl] =
                        make_uint4(*(unsigned*)&h0, *(unsigned*)&h1,
                                   *(unsigned*)&h2, *(unsigned*)&h3);
                }
            }
        } else if (writeStage && half == 0) {
            stage[(size_t)node * 16 + hl] = make_uint4(0u, 0u, 0u, 0u);
        }
    }
}

// ---------------- launch ------------------------------------------------------
extern "C" void kernel_launch(void* const* d_in, const int* in_sizes, int n_in,
                              void* d_out, int out_size) {
    const float* x    = (const float*)d_in[0];
    const void*  edge = d_in[1];
    const float* Wl1  = (const float*)d_in[2];
    const float* Wr1  = (const float*)d_in[3];
    const float* b1   = (const float*)d_in[4];
    const float* Wl2  = (const float*)d_in[5];
    const float* Wr2  = (const float*)d_in[6];
    const float* b2   = (const float*)d_in[7];
    float* out = (float*)d_out;

    const int N = in_sizes[0] / D;
    const int E = in_sizes[1] / 2;
    const int tiles = (N + 127) / 128;
    const int Npad = tiles * 128;
    const int scanBlocks = (N + 255) / 256;

    cudaFuncSetAttribute(gemm_tc_kernel,
                         cudaFuncAttributeMaxDynamicSharedMemorySize, SMEMB);

    // ---- fork: side branch = conv_w -> gemm1 (independent of CSR build) ----
    cudaEventRecord(s_fork, 0);                       // legacy default stream
    cudaStreamWaitEvent(s_side, s_fork, 0);
    conv_w_kernel<<<32, 256, 0, s_side>>>(Wl1, Wr1, Wl2, Wr2);
    gemm_tc_kernel<<<tiles, 512, SMEMB, s_side>>>(b1, 0, N, x);
    cudaEventRecord(s_join, s_side);

    // ---- main branch: graph preprocessing ----
    deg_kernel<<<1024, 256>>>(edge, E);
    scan1_kernel<<<scanBlocks, 256>>>(N);
    scan3_kernel<<<scanBlocks, 256>>>(N, E);
    build_csr_kernel<<<1024, 256>>>(edge, E);

    // ---- join, then the dependent tail ----
    cudaStreamWaitEvent(0, s_join, 0);
    pull_kernel<<<tiles * 16, 256>>>(nullptr, /*stage=*/1, N, Npad, /*relu=*/1);
    gemm_tc_kernel<<<tiles, 512, SMEMB>>>(b2, 1, N, nullptr);
    pull_kernel<<<tiles * 16, 256>>>(out, /*stage=*/0, N, Npad, /*relu=*/0);
}

// round 17
// speedup vs baseline: 1.1076x; 1.1027x over previous
#include <cuda_runtime.h>
#include <cuda_fp16.h>
#include <cstdint>

#define D 128
#define MAXN 100000
#define MAXE 1600000
#define MAXTILES ((MAXN + 127) / 128)   // 782

// ---------------- scratch (device globals; no allocations allowed) ----------
__device__ float g_inv [MAXN];                     // 1/max(deg,1)
__device__ int   g_cnt [MAXN];                     // degree histogram (kept 0)
__device__ int   g_off [MAXN + 1];                 // CSR offsets
__device__ int   g_cur [MAXN];                     // fill cursors
__device__ int   g_csr [MAXE];                     // src indices bucketed by dst
__device__ uint2 g_self16[(size_t)MAXN * 32];      // A @ Wr^T + b, fp16 rows
__device__ uint2 g_xl16[(size_t)MAXN * 32];        // messages A@Wl^T, fp16 rows
// fp16 staging, row-major [row][128] fp16 (16 uint4 per row) — layer-2 GEMM input
__device__ uint4 g_x16[(size_t)MAXTILES * 2048];
__device__ uint4 g_w16[2 * 4096];  // per layer: [Wl;Wr] stacked = 256 rows, fp16
__device__ int   g_bsum[512];

// ---------------- streams/events for fork-join capture ----------------------
static cudaStream_t s_side = nullptr;
static cudaEvent_t  s_fork = nullptr, s_join = nullptr;
namespace {
struct SideInit {
    SideInit() {
        cudaStreamCreateWithFlags(&s_side, cudaStreamNonBlocking);
        cudaEventCreateWithFlags(&s_fork, cudaEventDisableTiming);
        cudaEventCreateWithFlags(&s_join, cudaEventDisableTiming);
    }
};
SideInit s_sideInit;
}

// ---------------- small helpers ---------------------------------------------
__device__ __forceinline__ int load_idx(const void* p, int is64, long long i) {
    if (is64) return (int)((const long long*)p)[i];
    return ((const int*)p)[i];
}

// per-block probe: int64 edge buffer has all-zero high words in first 128 elems
__device__ __forceinline__ int probe_is64(const void* edge, int E) {
    int t = threadIdx.x;
    unsigned hw = 0;
    if (t < 128 && t < E) hw = ((const unsigned*)edge)[2 * t + 1];
    int any = __syncthreads_or(hw != 0);
    return !any;
}

// degree histogram, 4-way unrolled (g_cnt zero on entry; re-zeroed by scan3)
__global__ void deg_kernel(const void* __restrict__ edge, int E) {
    const int is64 = probe_is64(edge, E);
    const long long t0 = blockIdx.x * (long long)blockDim.x + threadIdx.x;
    const long long stride4 = ((long long)gridDim.x * blockDim.x) * 4;
    long long e = t0 * 4;
    for (; e + 4 <= E; e += stride4) {
        int d0 = load_idx(edge, is64, (long long)E + e + 0);
        int d1 = load_idx(edge, is64, (long long)E + e + 1);
        int d2 = load_idx(edge, is64, (long long)E + e + 2);
        int d3 = load_idx(edge, is64, (long long)E + e + 3);
        atomicAdd(&g_cnt[d0], 1);
        atomicAdd(&g_cnt[d1], 1);
        atomicAdd(&g_cnt[d2], 1);
        atomicAdd(&g_cnt[d3], 1);
    }
    for (; e < E; e++) {
        int d = load_idx(edge, is64, (long long)E + e);
        atomicAdd(&g_cnt[d], 1);
    }
}

// ---- scan: stage1 block sums, stage2 fused into stage3 ---------------------
__global__ void scan1_kernel(int N) {
    __shared__ int sh[256];
    int i = blockIdx.x * 256 + threadIdx.x;
    sh[threadIdx.x] = (i < N) ? g_cnt[i] : 0;
    __syncthreads();
#pragma unroll
    for (int s = 128; s > 0; s >>= 1) {
        if (threadIdx.x < s) sh[threadIdx.x] += sh[threadIdx.x + s];
        __syncthreads();
    }
    if (threadIdx.x == 0) g_bsum[blockIdx.x] = sh[0];
}

__global__ void scan3_kernel(int N, int E) {
    __shared__ int sh[256];
    __shared__ int red[256];
    const int t = threadIdx.x;
    const int i = blockIdx.x * 256 + t;

    int acc = 0;
    for (int j = t; j < blockIdx.x; j += 256) acc += g_bsum[j];
    red[t] = acc;
    __syncthreads();
#pragma unroll
    for (int s = 128; s > 0; s >>= 1) {
        if (t < s) red[t] += red[t + s];
        __syncthreads();
    }
    const int base = red[0];

    int v = (i < N) ? g_cnt[i] : 0;
    sh[t] = v;
    __syncthreads();
#pragma unroll
    for (int s = 1; s < 256; s <<= 1) {
        int u = (t >= s) ? sh[t - s] : 0;
        __syncthreads();
        sh[t] += u;
        __syncthreads();
    }
    if (i < N) {
        int excl = base + sh[t] - v;
        g_off[i] = excl;
        g_cur[i] = excl;
        g_inv[i] = 1.0f / fmaxf((float)v, 1.0f);
        g_cnt[i] = 0;                 // keep zeroed for the next call (replay)
    }
    if (i == N - 1) g_off[N] = E;
}

// CSR bucket fill, 2-way unrolled (atomic cursors)
__global__ void build_csr_kernel(const void* __restrict__ edge, int E) {
    const int is64 = probe_is64(edge, E);
    const long long t0 = blockIdx.x * (long long)blockDim.x + threadIdx.x;
    const long long stride2 = ((long long)gridDim.x * blockDim.x) * 2;
    long long e = t0 * 2;
    for (; e + 2 <= E; e += stride2) {
        int s0 = load_idx(edge, is64, e + 0);
        int s1 = load_idx(edge, is64, e + 1);
        int d0 = load_idx(edge, is64, (long long)E + e + 0);
        int d1 = load_idx(edge, is64, (long long)E + e + 1);
        int p0 = atomicAdd(&g_cur[d0], 1);
        int p1 = atomicAdd(&g_cur[d1], 1);
        g_csr[p0] = s0;
        g_csr[p1] = s1;
    }
    for (; e < E; e++) {
        int s = load_idx(edge, is64, e);
        int d = load_idx(edge, is64, (long long)E + e);
        int pos = atomicAdd(&g_cur[d], 1);
        g_csr[pos] = s;
    }
}

// ---------------- weight conversion: fp32 -> fp16 ---------------------------
__global__ void conv_w_kernel(const float* __restrict__ W0, const float* __restrict__ W1,
                              const float* __restrict__ W2, const float* __restrict__ W3) {
    int c = blockIdx.x * blockDim.x + threadIdx.x;   // 0 .. 4*2048-1
    if (c >= 4 * 2048) return;
    int which = c >> 11;
    int local = c & 2047;
    int row = local >> 4, kc = local & 15;
    const float* W = (which == 0) ? W0 : (which == 1) ? W1 : (which == 2) ? W2 : W3;
    const float4* ap = (const float4*)(W + (size_t)row * D + kc * 8);
    float4 a = ap[0], b = ap[1];
    float v[8] = {a.x, a.y, a.z, a.w, b.x, b.y, b.z, b.w};
    unsigned hw[4];
#pragma unroll
    for (int i = 0; i < 4; i++) {
        __half2 h = __floats2half2_rn(v[2*i], v[2*i+1]);
        hw[i] = *(unsigned*)&h;
    }
    int layer = which >> 1, half = which & 1;
    long long o = (long long)layer * 4096 + half * 2048 + local;
    g_w16[o] = make_uint4(hw[0], hw[1], hw[2], hw[3]);
}

// ---------------- mma.sync fp16 GEMM with ldmatrix ---------------------------
__device__ __forceinline__ void mma16816(float* acc, const unsigned* a,
                                         const unsigned* b) {
    asm volatile(
        "mma.sync.aligned.m16n8k16.row.col.f32.f16.f16.f32 "
        "{%0,%1,%2,%3}, {%4,%5,%6,%7}, {%8,%9}, {%0,%1,%2,%3};"
        : "+f"(acc[0]), "+f"(acc[1]), "+f"(acc[2]), "+f"(acc[3])
        : "r"(a[0]), "r"(a[1]), "r"(a[2]), "r"(a[3]), "r"(b[0]), "r"(b[1]));
}
__device__ __forceinline__ void ldsm4(unsigned* r, uint32_t a) {
    asm volatile("ldmatrix.sync.aligned.m8n8.x4.shared.b16 {%0,%1,%2,%3}, [%4];"
        : "=r"(r[0]), "=r"(r[1]), "=r"(r[2]), "=r"(r[3]) : "r"(a));
}
__device__ __forceinline__ uint32_t smem_u32(const void* p) {
    uint32_t a;
    asm("{ .reg .u64 t; cvta.to.shared.u64 t, %1; cvt.u32.u64 %0, t; }"
        : "=r"(a) : "l"(p));
    return a;
}
__device__ __forceinline__ void acc_m(float4& acc, uint2 m) {
    float2 f0 = __half22float2(*(__half2*)&m.x);
    float2 f1 = __half22float2(*(__half2*)&m.y);
    acc.x += f0.x; acc.y += f0.y; acc.z += f1.x; acc.w += f1.y;
}

// SMEM row = 272B (17 uint4): ldmatrix 8-row phases -> conflict-free
#define RS16 17
#define RSB  272
#define A4   0
#define W4L  2176
#define W4R  4352
#define SMEMB 104448

// dual-output GEMM: one block per 128-row tile; A staged once, both W tiles
// staged; two accumulation passes -> xl16 (Wl) and self16 (Wr + bias)
__global__ __launch_bounds__(512, 1)
void gemm_tc_kernel(const float* __restrict__ bias, int layer,
                    int N, const float* __restrict__ a32) {
    extern __shared__ uint4 smem4[];

    const int tid  = threadIdx.x;
    const int wid  = tid >> 5;
    const int lane = tid & 31;
    const int tile = blockIdx.x;

    const int mrow = (wid & 3) * 32;
    const int ncol = (wid >> 2) * 32;

    // ---- stage A and BOTH output W tiles ----
    {
        const uint4* wl = g_w16 + (size_t)layer * 4096;
        const uint4* wr = wl + 2048;
        if (a32) {
#pragma unroll
            for (int i = tid; i < 2048; i += 512) {
                int r = i >> 4, c = i & 15;
                int grow = tile * 128 + r;
                unsigned wd[4] = {0u, 0u, 0u, 0u};
                if (grow < N) {
                    const float4* ap = (const float4*)(a32 + (size_t)grow * D + c * 8);
                    float4 f0 = ap[0], f1 = ap[1];
                    __half2 h;
                    h = __floats2half2_rn(f0.x, f0.y); wd[0] = *(unsigned*)&h;
                    h = __floats2half2_rn(f0.z, f0.w); wd[1] = *(unsigned*)&h;
                    h = __floats2half2_rn(f1.x, f1.y); wd[2] = *(unsigned*)&h;
                    h = __floats2half2_rn(f1.z, f1.w); wd[3] = *(unsigned*)&h;
                }
                smem4[A4  + r * RS16 + c] = make_uint4(wd[0], wd[1], wd[2], wd[3]);
                smem4[W4L + r * RS16 + c] = wl[i];
                smem4[W4R + r * RS16 + c] = wr[i];
            }
        } else {
            const uint4* ga = g_x16 + (size_t)tile * 2048;
#pragma unroll
            for (int i = tid; i < 2048; i += 512) {
                int r = i >> 4, c = i & 15;
                smem4[A4  + r * RS16 + c] = ga[i];
                smem4[W4L + r * RS16 + c] = wl[i];
                smem4[W4R + r * RS16 + c] = wr[i];
            }
        }
    }
    __syncthreads();

    const uint32_t sb = smem_u32(smem4);
    const uint32_t aoff = (uint32_t)((mrow + (lane & 15)) * RSB + (lane >> 4) * 16);
    const uint32_t a0 = sb + A4 * 16 + aoff;
    const uint32_t a1 = a0 + 16 * RSB;
    const int msel = lane >> 3;
    const uint32_t woff = (uint32_t)((ncol + ((msel >> 1) * 8) + (lane & 7)) * RSB +
                                     (msel & 1) * 16);
    const int q = lane & 3, g = lane >> 2;

#pragma unroll
    for (int osel = 0; osel < 2; osel++) {
        const uint32_t w0 = sb + (osel ? W4R : W4L) * 16 + woff;
        const uint32_t w1 = w0 + 16 * RSB;

        float acc[2][4][4];
#pragma unroll
        for (int mt = 0; mt < 2; mt++)
#pragma unroll
            for (int nt = 0; nt < 4; nt++)
#pragma unroll
                for (int i = 0; i < 4; i++) acc[mt][nt][i] = 0.f;

#pragma unroll
        for (int kc = 0; kc < 8; kc++) {
            const uint32_t kb = kc * 32;
            unsigned af[2][4], wf[2][4];
            ldsm4(af[0], a0 + kb); ldsm4(af[1], a1 + kb);
            ldsm4(wf[0], w0 + kb); ldsm4(wf[1], w1 + kb);
#pragma unroll
            for (int mt = 0; mt < 2; mt++)
#pragma unroll
                for (int nt = 0; nt < 4; nt++)
                    mma16816(acc[mt][nt], af[mt], &wf[nt >> 1][(nt & 1) * 2]);
        }

        __half* op = (__half*)(osel ? g_self16 : g_xl16);
#pragma unroll
        for (int nt = 0; nt < 4; nt++) {
            int col = ncol + nt * 8 + q * 2;
            float b0 = 0.f, b1 = 0.f;
            if (osel) { b0 = __ldg(bias + col); b1 = __ldg(bias + col + 1); }
#pragma unroll
            for (int mt = 0; mt < 2; mt++) {
                int r = tile * 128 + mrow + mt * 16 + g;
                if (r < N)
                    *(__half2*)(op + (size_t)r * D + col) =
                        __floats2half2_rn(acc[mt][nt][0] + b0, acc[mt][nt][1] + b1);
                if (r + 8 < N)
                    *(__half2*)(op + (size_t)(r + 8) * D + col) =
                        __floats2half2_rn(acc[mt][nt][2] + b0, acc[mt][nt][3] + b1);
            }
        }
    }
}

// ---------------- CSR pull: out = [relu](self + mean_agg(xl16)) -------------
// warp per node; fp16 gather, fp32 accumulate; 8-wide MLP batching.
// 32-bit element offsets (s<<5)+lane keep the address math on the ALU-cheap path.
__global__ void pull_kernel(float* __restrict__ out32, int writeStage,
                            int N, int Npad, int doRelu) {
    const unsigned lane = threadIdx.x & 31;
    long long w  = (blockIdx.x * (long long)blockDim.x + threadIdx.x) >> 5;
    long long nw = ((long long)gridDim.x * blockDim.x) >> 5;

    uint2* stage = (uint2*)g_x16;

    for (long long node = w; node < Npad; node += nw) {
        if (node < N) {
            const int beg = g_off[node], end = g_off[node + 1];
            float4 acc = make_float4(0.f, 0.f, 0.f, 0.f);
            int e = beg;
            for (; e + 8 <= end; e += 8) {
                unsigned s0 = (unsigned)__ldg(g_csr + e + 0);
                unsigned s1 = (unsigned)__ldg(g_csr + e + 1);
                unsigned s2 = (unsigned)__ldg(g_csr + e + 2);
                unsigned s3 = (unsigned)__ldg(g_csr + e + 3);
                unsigned s4 = (unsigned)__ldg(g_csr + e + 4);
                unsigned s5 = (unsigned)__ldg(g_csr + e + 5);
                unsigned s6 = (unsigned)__ldg(g_csr + e + 6);
                unsigned s7 = (unsigned)__ldg(g_csr + e + 7);
                uint2 m0 = g_xl16[(s0 << 5) + lane];
                uint2 m1 = g_xl16[(s1 << 5) + lane];
                uint2 m2 = g_xl16[(s2 << 5) + lane];
                uint2 m3 = g_xl16[(s3 << 5) + lane];
                uint2 m4 = g_xl16[(s4 << 5) + lane];
                uint2 m5 = g_xl16[(s5 << 5) + lane];
                uint2 m6 = g_xl16[(s6 << 5) + lane];
                uint2 m7 = g_xl16[(s7 << 5) + lane];
                acc_m(acc, m0); acc_m(acc, m1); acc_m(acc, m2); acc_m(acc, m3);
                acc_m(acc, m4); acc_m(acc, m5); acc_m(acc, m6); acc_m(acc, m7);
            }
            if (e + 4 <= end) {
                unsigned s0 = (unsigned)__ldg(g_csr + e + 0);
                unsigned s1 = (unsigned)__ldg(g_csr + e + 1);
                unsigned s2 = (unsigned)__ldg(g_csr + e + 2);
                unsigned s3 = (unsigned)__ldg(g_csr + e + 3);
                uint2 m0 = g_xl16[(s0 << 5) + lane];
                uint2 m1 = g_xl16[(s1 << 5) + lane];
                uint2 m2 = g_xl16[(s2 << 5) + lane];
                uint2 m3 = g_xl16[(s3 << 5) + lane];
                acc_m(acc, m0); acc_m(acc, m1); acc_m(acc, m2); acc_m(acc, m3);
                e += 4;
            }
            for (; e < end; e++) {
                unsigned s = (unsigned)__ldg(g_csr + e);
                acc_m(acc, g_xl16[(s << 5) + lane]);
            }
            float inv = g_inv[node];
            uint2 s16 = g_self16[((unsigned)node << 5) + lane];
            float2 sv0 = __half22float2(*(__half2*)&s16.x);
            float2 sv1 = __half22float2(*(__half2*)&s16.y);
            float4 o;
            o.x = sv0.x + acc.x * inv; o.y = sv0.y + acc.y * inv;
            o.z = sv1.x + acc.z * inv; o.w = sv1.y + acc.w * inv;
            if (doRelu) {
                o.x = fmaxf(o.x, 0.f); o.y = fmaxf(o.y, 0.f);
                o.z = fmaxf(o.z, 0.f); o.w = fmaxf(o.w, 0.f);
            }
            if (out32)
                *(float4*)(out32 + (size_t)node * D + lane * 4) = o;
            if (writeStage) {
                uint2 p;
                __half2 h0 = __floats2half2_rn(o.x, o.y);
                __half2 h1 = __floats2half2_rn(o.z, o.w);
                p.x = *(unsigned*)&h0; p.y = *(unsigned*)&h1;
                stage[((unsigned)node << 5) + lane] = p;
            }
        } else if (writeStage) {
            stage[((unsigned)node << 5) + lane] = make_uint2(0u, 0u);
        }
    }
}

// ---------------- launch ------------------------------------------------------
extern "C" void kernel_launch(void* const* d_in, const int* in_sizes, int n_in,
                              void* d_out, int out_size) {
    const float* x    = (const float*)d_in[0];
    const void*  edge = d_in[1];
    const float* Wl1  = (const float*)d_in[2];
    const float* Wr1  = (const float*)d_in[3];
    const float* b1   = (const float*)d_in[4];
    const float* Wl2  = (const float*)d_in[5];
    const float* Wr2  = (const float*)d_in[6];
    const float* b2   = (const float*)d_in[7];
    float* out = (float*)d_out;

    const int N = in_sizes[0] / D;
    const int E = in_sizes[1] / 2;
    const int tiles = (N + 127) / 128;
    const int Npad = tiles * 128;
    const int scanBlocks = (N + 255) / 256;

    cudaFuncSetAttribute(gemm_tc_kernel,
                         cudaFuncAttributeMaxDynamicSharedMemorySize, SMEMB);

    // ---- fork: side branch = conv_w -> gemm1 (independent of CSR build) ----
    cudaEventRecord(s_fork, 0);                       // legacy default stream
    cudaStreamWaitEvent(s_side, s_fork, 0);
    conv_w_kernel<<<32, 256, 0, s_side>>>(Wl1, Wr1, Wl2, Wr2);
    gemm_tc_kernel<<<tiles, 512, SMEMB, s_side>>>(b1, 0, N, x);
    cudaEventRecord(s_join, s_side);

    // ---- main branch: graph preprocessing ----
    deg_kernel<<<1024, 256>>>(edge, E);
    scan1_kernel<<<scanBlocks, 256>>>(N);
    scan3_kernel<<<scanBlocks, 256>>>(N, E);
    build_csr_kernel<<<1024, 256>>>(edge, E);

    // ---- join, then the dependent tail ----
    cudaStreamWaitEvent(0, s_join, 0);
    pull_kernel<<<tiles * 16, 256>>>(nullptr, /*stage=*/1, N, Npad, /*relu=*/1);
    gemm_tc_kernel<<<tiles, 512, SMEMB>>>(b2, 1, N, nullptr);
    pull_kernel<<<tiles * 16, 256>>>(out, /*stage=*/0, N, Npad, /*relu=*/0);
}